// round 14
// baseline (speedup 1.0000x reference)
#include <cuda_runtime.h>

#define BLK 128   // 8 chains x 16 heads

// transformed weights: matrix-rep coords. coord(r,s,im) = (r*4+s)*2 + im
__device__ float g_Win2[16 * 6 * 32];   // [h][d][coord]
__device__ float g_bin2[16 * 32];       // [h][coord]
__device__ float g_Wout2[16 * 6 * 32];  // [h][d][coord]  (includes 1/4 factor)

// ---------------------------------------------------------------------------
// prep: build blade matrices of Cl(4,1) in M4(C), fold basis change into
// the weights. Runs every launch (deterministic, trivial cost).
// ---------------------------------------------------------------------------
__global__ void prep_kernel(const float* __restrict__ Win,    // [6,512]
                            const float* __restrict__ bin,    // [512]
                            const float* __restrict__ Wout)   // [512,6]
{
    __shared__ float B[32][32];   // blade -> 32 matrix coords

    if (threadIdx.x == 0) {
        float gre[5][4][4], gim[5][4][4];
        for (int i = 0; i < 5; i++)
            for (int r = 0; r < 4; r++)
                for (int s = 0; s < 4; s++) { gre[i][r][s] = 0.f; gim[i][r][s] = 0.f; }
        // g0 = gamma1
        gre[0][0][3] = 1; gre[0][1][2] = 1; gre[0][2][1] = 1; gre[0][3][0] = 1;
        // g1 = gamma2
        gim[1][0][3] = -1; gim[1][1][2] = 1; gim[1][2][1] = -1; gim[1][3][0] = 1;
        // g2 = gamma3
        gre[2][0][2] = 1; gre[2][1][3] = -1; gre[2][2][0] = 1; gre[2][3][1] = -1;
        // g3 = gamma4 (square +1)
        gim[3][0][2] = 1; gim[3][1][3] = 1; gim[3][2][0] = -1; gim[3][3][1] = -1;
        // g4 = e5 = i*g0*g1*g2*g3 = diag(i,i,-i,-i)  (square -1)
        gim[4][0][0] = 1; gim[4][1][1] = 1; gim[4][2][2] = -1; gim[4][3][3] = -1;

        for (int a = 0; a < 32; a++) {
            float mre[4][4], mim[4][4];
            for (int r = 0; r < 4; r++)
                for (int s = 0; s < 4; s++) { mre[r][s] = (r == s) ? 1.f : 0.f; mim[r][s] = 0.f; }
            for (int i = 0; i < 5; i++) {
                if (!((a >> i) & 1)) continue;
                float tre[4][4], tim[4][4];
                for (int r = 0; r < 4; r++)
                    for (int s = 0; s < 4; s++) {
                        float xr = 0.f, xi = 0.f;
                        for (int k = 0; k < 4; k++) {
                            xr += mre[r][k] * gre[i][k][s] - mim[r][k] * gim[i][k][s];
                            xi += mre[r][k] * gim[i][k][s] + mim[r][k] * gre[i][k][s];
                        }
                        tre[r][s] = xr; tim[r][s] = xi;
                    }
                for (int r = 0; r < 4; r++)
                    for (int s = 0; s < 4; s++) { mre[r][s] = tre[r][s]; mim[r][s] = tim[r][s]; }
            }
            for (int r = 0; r < 4; r++)
                for (int s = 0; s < 4; s++) {
                    B[a][(r * 4 + s) * 2]     = mre[r][s];
                    B[a][(r * 4 + s) * 2 + 1] = mim[r][s];
                }
        }
    }
    __syncthreads();

    for (int idx = threadIdx.x; idx < 3072; idx += blockDim.x) {
        int d = idx / 512, rem = idx - d * 512;
        int h = rem >> 5, coord = rem & 31;
        float s = 0.f;
        for (int c = 0; c < 32; c++)
            s += Win[d * 512 + h * 32 + c] * B[c][coord];
        g_Win2[(h * 6 + d) * 32 + coord] = s;
    }
    for (int idx = threadIdx.x; idx < 512; idx += blockDim.x) {
        int h = idx >> 5, coord = idx & 31;
        float s = 0.f;
        for (int c = 0; c < 32; c++)
            s += bin[h * 32 + c] * B[c][coord];
        g_bin2[idx] = s;
    }
    for (int idx = threadIdx.x; idx < 3072; idx += blockDim.x) {
        int h = idx / 192, rem = idx - h * 192;
        int d = rem >> 5, coord = rem & 31;
        float s = 0.f;
        for (int c = 0; c < 32; c++)
            s += B[c][coord] * Wout[(h * 32 + c) * 6 + d];
        g_Wout2[(h * 6 + d) * 32 + coord] = 0.25f * s;
    }
}

// ---------------------------------------------------------------------------
// main scan. thread = (chain, head), psi = 4x4 complex matrix in registers.
// Loop over 128 step-PAIRS: both embeds computed up front (off the psi
// chain), projections on unnormalized acc, one barrier per pair with
// compile-time-indexed ping-pong partial buffers.
// shapes: B=16, S=256, N=64, D=6, H=16; x strides: b 98304, s 384, n 6
// ---------------------------------------------------------------------------
__global__ __launch_bounds__(BLK, 1)
void versor_kernel(const float* __restrict__ x,
                   const float* __restrict__ bout,   // [6]
                   float* __restrict__ out)
{
    __shared__ __align__(16) float sWin[16 * 196];      // 12544 B
    __shared__ __align__(16) float sWout[16 * 196];     // 12544 B
    __shared__ __align__(16) float sPart[2][2][16][50]; // 12800 B

    const int tid = threadIdx.x;
    const int ci  = tid & 7;        // chain within block
    const int h   = tid >> 3;       // head
    const int b   = blockIdx.x >> 3;
    const int n0  = (blockIdx.x & 7) * 8;

    // ---- stage transformed weights into shared ----
    for (int i = tid; i < 3072; i += BLK) {
        int hh = i / 192, rr = i - hh * 192;
        sWin[hh * 196 + rr]  = g_Win2[i];
        sWout[hh * 196 + rr] = g_Wout2[i];
    }
    __syncthreads();

    // bias into registers (off the per-step LDS path)
    float binr[32];
#pragma unroll
    for (int c = 0; c < 32; c++) binr[c] = __ldg(&g_bin2[h * 32 + c]);

    const float* xchain = x + (size_t)b * 98304 + (size_t)(n0 + ci) * 6;
    const float* wi = sWin  + h * 196;
    const float* wo = sWout + h * 196;

    // reducer role (threads 0..47): chain rci, component rd
    const int  rci = tid / 6;
    const int  rd  = tid - rci * 6;
    const bool is_red = (tid < 48);
    const float boutr = __ldg(bout + (is_red ? rd : 0));
    const size_t obase = (size_t)b * 98304 + (size_t)(n0 + (is_red ? rci : 0)) * 6 + rd;

    // psi matrix coords; psi0 = identity
    float P[32];
#pragma unroll
    for (int k = 0; k < 32; k++) P[k] = 0.0f;
    P[0] = 1.0f; P[10] = 1.0f; P[20] = 1.0f; P[30] = 1.0f;

    // ---- prefetch x for pair 0; reducer prefetch output rows 0,1 ----
    float2 a0v = __ldg((const float2*)xchain);
    float2 a1v = __ldg((const float2*)xchain + 1);
    float2 a2v = __ldg((const float2*)xchain + 2);
    float2 b0v = __ldg((const float2*)(xchain + 384));
    float2 b1v = __ldg((const float2*)(xchain + 384) + 1);
    float2 b2v = __ldg((const float2*)(xchain + 384) + 2);
    float rxA = 0.f, rxB = 0.f;
    if (is_red) {
        rxA = __ldg(x + obase);
        rxB = __ldg(x + obase + 384);
    }

    for (int tp = 0; tp < 128; tp++) {
        const float xvA[6] = { a0v.x, a0v.y, a1v.x, a1v.y, a2v.x, a2v.y };
        const float xvB[6] = { b0v.x, b0v.y, b1v.x, b1v.y, b2v.x, b2v.y };

        // ---- prefetch x for next pair ----
        {
            int tn = (tp < 127) ? (2 * tp + 2) : 254;
            const float* pA = xchain + (size_t)tn * 384;
            a0v = __ldg((const float2*)pA);
            a1v = __ldg((const float2*)pA + 1);
            a2v = __ldg((const float2*)pA + 2);
            const float* pB = pA + 384;
            b0v = __ldg((const float2*)pB);
            b1v = __ldg((const float2*)pB + 1);
            b2v = __ldg((const float2*)pB + 2);
        }

        // ---- BOTH embeds up front (independent of psi chain) ----
        float uA[32], uB[32];
        {
            float xa = xvA[0], xb = xvB[0];
#pragma unroll
            for (int c4 = 0; c4 < 8; c4++) {
                float4 w = *(const float4*)(wi + c4 * 4);
                uA[c4 * 4 + 0] = fmaf(xa, w.x, binr[c4 * 4 + 0]);
                uA[c4 * 4 + 1] = fmaf(xa, w.y, binr[c4 * 4 + 1]);
                uA[c4 * 4 + 2] = fmaf(xa, w.z, binr[c4 * 4 + 2]);
                uA[c4 * 4 + 3] = fmaf(xa, w.w, binr[c4 * 4 + 3]);
                uB[c4 * 4 + 0] = fmaf(xb, w.x, binr[c4 * 4 + 0]);
                uB[c4 * 4 + 1] = fmaf(xb, w.y, binr[c4 * 4 + 1]);
                uB[c4 * 4 + 2] = fmaf(xb, w.z, binr[c4 * 4 + 2]);
                uB[c4 * 4 + 3] = fmaf(xb, w.w, binr[c4 * 4 + 3]);
            }
        }
#pragma unroll
        for (int d = 1; d < 6; d++) {
            float xa = xvA[d], xb = xvB[d];
#pragma unroll
            for (int c4 = 0; c4 < 8; c4++) {
                float4 w = *(const float4*)(wi + d * 32 + c4 * 4);
                uA[c4 * 4 + 0] = fmaf(xa, w.x, uA[c4 * 4 + 0]);
                uA[c4 * 4 + 1] = fmaf(xa, w.y, uA[c4 * 4 + 1]);
                uA[c4 * 4 + 2] = fmaf(xa, w.z, uA[c4 * 4 + 2]);
                uA[c4 * 4 + 3] = fmaf(xa, w.w, uA[c4 * 4 + 3]);
                uB[c4 * 4 + 0] = fmaf(xb, w.x, uB[c4 * 4 + 0]);
                uB[c4 * 4 + 1] = fmaf(xb, w.y, uB[c4 * 4 + 1]);
                uB[c4 * 4 + 2] = fmaf(xb, w.z, uB[c4 * 4 + 2]);
                uB[c4 * 4 + 3] = fmaf(xb, w.w, uB[c4 * 4 + 3]);
            }
        }
        uA[0] += 1.0f; uA[10] += 1.0f; uA[20] += 1.0f; uA[30] += 1.0f;
        uB[0] += 1.0f; uB[10] += 1.0f; uB[20] += 1.0f; uB[30] += 1.0f;

        const int gb = tp & 1;

        // ================= STEP A =================
        {
            float acc[32];
#pragma unroll
            for (int r = 0; r < 4; r++) {
#pragma unroll
                for (int s = 0; s < 4; s++) {
                    float cre = 0.f, cim = 0.f;
#pragma unroll
                    for (int k = 0; k < 4; k++) {
                        float are = uA[(r * 4 + k) * 2], aim = uA[(r * 4 + k) * 2 + 1];
                        float bre = P[(k * 4 + s) * 2], bim = P[(k * 4 + s) * 2 + 1];
                        cre = fmaf(are, bre, cre);
                        cre = fmaf(-aim, bim, cre);
                        cim = fmaf(are, bim, cim);
                        cim = fmaf(aim, bre, cim);
                    }
                    acc[(r * 4 + s) * 2]     = cre;
                    acc[(r * 4 + s) * 2 + 1] = cim;
                }
            }
            float s0 = 0.f, s1 = 0.f, s2 = 0.f, s3 = 0.f;
#pragma unroll
            for (int c = 0; c < 32; c += 4) {
                s0 = fmaf(acc[c + 0], acc[c + 0], s0);
                s1 = fmaf(acc[c + 1], acc[c + 1], s1);
                s2 = fmaf(acc[c + 2], acc[c + 2], s2);
                s3 = fmaf(acc[c + 3], acc[c + 3], s3);
            }
            float rn = rsqrtf(0.25f * ((s0 + s1) + (s2 + s3)));

            float pd[6];
#pragma unroll
            for (int d = 0; d < 6; d++) {
                float p0 = 0.f, p1 = 0.f, p2 = 0.f, p3 = 0.f;
#pragma unroll
                for (int c4 = 0; c4 < 8; c4++) {
                    float4 w = *(const float4*)(wo + d * 32 + c4 * 4);
                    p0 = fmaf(acc[c4 * 4 + 0], w.x, p0);
                    p1 = fmaf(acc[c4 * 4 + 1], w.y, p1);
                    p2 = fmaf(acc[c4 * 4 + 2], w.z, p2);
                    p3 = fmaf(acc[c4 * 4 + 3], w.w, p3);
                }
                pd[d] = ((p0 + p1) + (p2 + p3)) * rn;
            }
#pragma unroll
            for (int c = 0; c < 32; c++) P[c] = acc[c] * rn;

            float2* pp = (float2*)&sPart[gb][0][h][ci * 6];
            pp[0] = make_float2(pd[0], pd[1]);
            pp[1] = make_float2(pd[2], pd[3]);
            pp[2] = make_float2(pd[4], pd[5]);
        }

        // ================= STEP B =================
        {
            float acc[32];
#pragma unroll
            for (int r = 0; r < 4; r++) {
#pragma unroll
                for (int s = 0; s < 4; s++) {
                    float cre = 0.f, cim = 0.f;
#pragma unroll
                    for (int k = 0; k < 4; k++) {
                        float are = uB[(r * 4 + k) * 2], aim = uB[(r * 4 + k) * 2 + 1];
                        float bre = P[(k * 4 + s) * 2], bim = P[(k * 4 + s) * 2 + 1];
                        cre = fmaf(are, bre, cre);
                        cre = fmaf(-aim, bim, cre);
                        cim = fmaf(are, bim, cim);
                        cim = fmaf(aim, bre, cim);
                    }
                    acc[(r * 4 + s) * 2]     = cre;
                    acc[(r * 4 + s) * 2 + 1] = cim;
                }
            }
            float s0 = 0.f, s1 = 0.f, s2 = 0.f, s3 = 0.f;
#pragma unroll
            for (int c = 0; c < 32; c += 4) {
                s0 = fmaf(acc[c + 0], acc[c + 0], s0);
                s1 = fmaf(acc[c + 1], acc[c + 1], s1);
                s2 = fmaf(acc[c + 2], acc[c + 2], s2);
                s3 = fmaf(acc[c + 3], acc[c + 3], s3);
            }
            float rn = rsqrtf(0.25f * ((s0 + s1) + (s2 + s3)));

            float pd[6];
#pragma unroll
            for (int d = 0; d < 6; d++) {
                float p0 = 0.f, p1 = 0.f, p2 = 0.f, p3 = 0.f;
#pragma unroll
                for (int c4 = 0; c4 < 8; c4++) {
                    float4 w = *(const float4*)(wo + d * 32 + c4 * 4);
                    p0 = fmaf(acc[c4 * 4 + 0], w.x, p0);
                    p1 = fmaf(acc[c4 * 4 + 1], w.y, p1);
                    p2 = fmaf(acc[c4 * 4 + 2], w.z, p2);
                    p3 = fmaf(acc[c4 * 4 + 3], w.w, p3);
                }
                pd[d] = ((p0 + p1) + (p2 + p3)) * rn;
            }
#pragma unroll
            for (int c = 0; c < 32; c++) P[c] = acc[c] * rn;

            float2* pp = (float2*)&sPart[gb][1][h][ci * 6];
            pp[0] = make_float2(pd[0], pd[1]);
            pp[1] = make_float2(pd[2], pd[3]);
            pp[2] = make_float2(pd[4], pd[5]);
        }

        // ---- barrier + reduce once per pair ----
        __syncthreads();
        if (is_red) {
            float sa = boutr + rxA;
            float sb = boutr + rxB;
#pragma unroll
            for (int hh = 0; hh < 16; hh++) {
                sa += sPart[gb][0][hh][rci * 6 + rd];
                sb += sPart[gb][1][hh][rci * 6 + rd];
            }
            out[obase + (size_t)(2 * tp) * 384]     = sa;
            out[obase + (size_t)(2 * tp + 1) * 384] = sb;
            int ta = (tp < 127) ? (2 * tp + 2) : 254;
            rxA = __ldg(x + obase + (size_t)ta * 384);
            rxB = __ldg(x + obase + (size_t)(ta + 1) * 384);
        }
    }
}

extern "C" void kernel_launch(void* const* d_in, const int* in_sizes, int n_in,
                              void* d_out, int out_size)
{
    const float* x    = (const float*)d_in[0];
    const float* Win  = (const float*)d_in[1];
    const float* bin  = (const float*)d_in[2];
    const float* Wout = (const float*)d_in[3];
    const float* bout = (const float*)d_in[4];
    float* out = (float*)d_out;

    prep_kernel<<<1, 256>>>(Win, bin, Wout);
    versor_kernel<<<128, BLK>>>(x, bout, out);
}

// round 15
// speedup vs baseline: 1.1482x; 1.1482x over previous
#include <cuda_runtime.h>

#define BLK 64   // 4 chains x 16 heads; 2 independent blocks per SM

// transformed weights: matrix-rep coords. coord(r,s,im) = (r*4+s)*2 + im
__device__ float g_Win2[16 * 6 * 32];   // [h][d][coord]
__device__ float g_bin2[16 * 32];       // [h][coord]
__device__ float g_Wout2[16 * 6 * 32];  // [h][d][coord]  (includes 1/4 factor)

// ---------------------------------------------------------------------------
// prep: build blade matrices of Cl(4,1) in M4(C), fold basis change into
// the weights. Runs every launch (deterministic, trivial cost).
// ---------------------------------------------------------------------------
__global__ void prep_kernel(const float* __restrict__ Win,    // [6,512]
                            const float* __restrict__ bin,    // [512]
                            const float* __restrict__ Wout)   // [512,6]
{
    __shared__ float B[32][32];   // blade -> 32 matrix coords

    if (threadIdx.x == 0) {
        float gre[5][4][4], gim[5][4][4];
        for (int i = 0; i < 5; i++)
            for (int r = 0; r < 4; r++)
                for (int s = 0; s < 4; s++) { gre[i][r][s] = 0.f; gim[i][r][s] = 0.f; }
        // g0 = gamma1
        gre[0][0][3] = 1; gre[0][1][2] = 1; gre[0][2][1] = 1; gre[0][3][0] = 1;
        // g1 = gamma2
        gim[1][0][3] = -1; gim[1][1][2] = 1; gim[1][2][1] = -1; gim[1][3][0] = 1;
        // g2 = gamma3
        gre[2][0][2] = 1; gre[2][1][3] = -1; gre[2][2][0] = 1; gre[2][3][1] = -1;
        // g3 = gamma4 (square +1)
        gim[3][0][2] = 1; gim[3][1][3] = 1; gim[3][2][0] = -1; gim[3][3][1] = -1;
        // g4 = e5 = i*g0*g1*g2*g3 = diag(i,i,-i,-i)  (square -1)
        gim[4][0][0] = 1; gim[4][1][1] = 1; gim[4][2][2] = -1; gim[4][3][3] = -1;

        for (int a = 0; a < 32; a++) {
            float mre[4][4], mim[4][4];
            for (int r = 0; r < 4; r++)
                for (int s = 0; s < 4; s++) { mre[r][s] = (r == s) ? 1.f : 0.f; mim[r][s] = 0.f; }
            for (int i = 0; i < 5; i++) {
                if (!((a >> i) & 1)) continue;
                float tre[4][4], tim[4][4];
                for (int r = 0; r < 4; r++)
                    for (int s = 0; s < 4; s++) {
                        float xr = 0.f, xi = 0.f;
                        for (int k = 0; k < 4; k++) {
                            xr += mre[r][k] * gre[i][k][s] - mim[r][k] * gim[i][k][s];
                            xi += mre[r][k] * gim[i][k][s] + mim[r][k] * gre[i][k][s];
                        }
                        tre[r][s] = xr; tim[r][s] = xi;
                    }
                for (int r = 0; r < 4; r++)
                    for (int s = 0; s < 4; s++) { mre[r][s] = tre[r][s]; mim[r][s] = tim[r][s]; }
            }
            for (int r = 0; r < 4; r++)
                for (int s = 0; s < 4; s++) {
                    B[a][(r * 4 + s) * 2]     = mre[r][s];
                    B[a][(r * 4 + s) * 2 + 1] = mim[r][s];
                }
        }
    }
    __syncthreads();

    for (int idx = threadIdx.x; idx < 3072; idx += blockDim.x) {
        int d = idx / 512, rem = idx - d * 512;
        int h = rem >> 5, coord = rem & 31;
        float s = 0.f;
        for (int c = 0; c < 32; c++)
            s += Win[d * 512 + h * 32 + c] * B[c][coord];
        g_Win2[(h * 6 + d) * 32 + coord] = s;
    }
    for (int idx = threadIdx.x; idx < 512; idx += blockDim.x) {
        int h = idx >> 5, coord = idx & 31;
        float s = 0.f;
        for (int c = 0; c < 32; c++)
            s += bin[h * 32 + c] * B[c][coord];
        g_bin2[idx] = s;
    }
    for (int idx = threadIdx.x; idx < 3072; idx += blockDim.x) {
        int h = idx / 192, rem = idx - h * 192;
        int d = rem >> 5, coord = rem & 31;
        float s = 0.f;
        for (int c = 0; c < 32; c++)
            s += B[c][coord] * Wout[(h * 32 + c) * 6 + d];
        g_Wout2[(h * 6 + d) * 32 + coord] = 0.25f * s;
    }
}

// ---------------------------------------------------------------------------
// main scan. thread = (chain, head), psi = 4x4 complex matrix in registers.
// 64-thread blocks (4 chains x 16 heads): barriers span only 2 warps, and
// 2 independent blocks per SM interleave through each other's barrier waits.
// x prefetched 1 step ahead; projection on unnormalized acc; barrier every
// 2 steps with ping-pong partial buffers.
// shapes: B=16, S=256, N=64, D=6, H=16; x strides: b 98304, s 384, n 6
// ---------------------------------------------------------------------------
__global__ __launch_bounds__(BLK, 2)
void versor_kernel(const float* __restrict__ x,
                   const float* __restrict__ bout,   // [6]
                   float* __restrict__ out)
{
    __shared__ __align__(16) float sWin[16 * 196];      // 12544 B
    __shared__ __align__(16) float sWout[16 * 196];     // 12544 B
    __shared__ __align__(16) float sPart[2][2][16][26]; // 6656 B -> 31744 B total

    const int tid = threadIdx.x;
    const int ci  = tid & 3;        // chain within block (4)
    const int h   = tid >> 2;       // head (warp0: h0-7, warp1: h8-15)
    const int b   = blockIdx.x >> 4;
    const int n0  = (blockIdx.x & 15) * 4;

    // ---- stage transformed weights into shared ----
    for (int i = tid; i < 3072; i += BLK) {
        int hh = i / 192, rr = i - hh * 192;
        sWin[hh * 196 + rr]  = g_Win2[i];
        sWout[hh * 196 + rr] = g_Wout2[i];
    }
    __syncthreads();

    // bias into registers (off the per-step LDS path)
    float binr[32];
#pragma unroll
    for (int c = 0; c < 32; c++) binr[c] = __ldg(&g_bin2[h * 32 + c]);

    const float* xchain = x + (size_t)b * 98304 + (size_t)(n0 + ci) * 6;
    const float* wi = sWin  + h * 196;
    const float* wo = sWout + h * 196;

    // reducer role (threads 0..23): chain rci, component rd
    const int  rci = tid / 6;
    const int  rd  = tid - rci * 6;
    const bool is_red = (tid < 24);
    const float boutr = __ldg(bout + (is_red ? rd : 0));
    const size_t obase = (size_t)b * 98304 + (size_t)(n0 + (is_red ? rci : 0)) * 6 + rd;

    // psi matrix coords; psi0 = identity
    float P[32];
#pragma unroll
    for (int k = 0; k < 32; k++) P[k] = 0.0f;
    P[0] = 1.0f; P[10] = 1.0f; P[20] = 1.0f; P[30] = 1.0f;

    // ---- prefetch t=0 x; reducer prefetch output rows 0,1 ----
    const float2* xp2 = (const float2*)xchain;
    float2 nb0 = __ldg(xp2), nb1 = __ldg(xp2 + 1), nb2 = __ldg(xp2 + 2);
    float rxA = 0.f, rxB = 0.f;
    if (is_red) {
        rxA = __ldg(x + obase);
        rxB = __ldg(x + obase + 384);
    }

    for (int t = 0; t < 256; t++) {
        const float xv[6] = { nb0.x, nb0.y, nb1.x, nb1.y, nb2.x, nb2.y };

        // ---- prefetch t+1 (latency overlaps this whole step) ----
        {
            int tn = (t < 255) ? (t + 1) : 255;
            const float2* np = (const float2*)(xchain + (size_t)tn * 384);
            nb0 = __ldg(np); nb1 = __ldg(np + 1); nb2 = __ldg(np + 2);
        }

        // ---- embed into matrix coords: U = bin' + x @ Win' ----
        float u[32];
        {
            float x0 = xv[0];
#pragma unroll
            for (int c4 = 0; c4 < 8; c4++) {
                float4 w = *(const float4*)(wi + c4 * 4);
                u[c4 * 4 + 0] = fmaf(x0, w.x, binr[c4 * 4 + 0]);
                u[c4 * 4 + 1] = fmaf(x0, w.y, binr[c4 * 4 + 1]);
                u[c4 * 4 + 2] = fmaf(x0, w.z, binr[c4 * 4 + 2]);
                u[c4 * 4 + 3] = fmaf(x0, w.w, binr[c4 * 4 + 3]);
            }
        }
#pragma unroll
        for (int d = 1; d < 6; d++) {
            float xd = xv[d];
#pragma unroll
            for (int c4 = 0; c4 < 8; c4++) {
                float4 w = *(const float4*)(wi + d * 32 + c4 * 4);
                u[c4 * 4 + 0] = fmaf(xd, w.x, u[c4 * 4 + 0]);
                u[c4 * 4 + 1] = fmaf(xd, w.y, u[c4 * 4 + 1]);
                u[c4 * 4 + 2] = fmaf(xd, w.z, u[c4 * 4 + 2]);
                u[c4 * 4 + 3] = fmaf(xd, w.w, u[c4 * 4 + 3]);
            }
        }

        // ---- +identity; delta_r pre-normalize cancels (GP bilinear + post-norm) ----
        u[0] += 1.0f; u[10] += 1.0f; u[20] += 1.0f; u[30] += 1.0f;

        // ---- GP: acc = U * P (4x4 complex matmul) ----
        float acc[32];
#pragma unroll
        for (int r = 0; r < 4; r++) {
#pragma unroll
            for (int s = 0; s < 4; s++) {
                float cre = 0.f, cim = 0.f;
#pragma unroll
                for (int k = 0; k < 4; k++) {
                    float are = u[(r * 4 + k) * 2], aim = u[(r * 4 + k) * 2 + 1];
                    float bre = P[(k * 4 + s) * 2], bim = P[(k * 4 + s) * 2 + 1];
                    cre = fmaf(are, bre, cre);
                    cre = fmaf(-aim, bim, cre);
                    cim = fmaf(are, bim, cim);
                    cim = fmaf(aim, bre, cim);
                }
                acc[(r * 4 + s) * 2]     = cre;
                acc[(r * 4 + s) * 2 + 1] = cim;
            }
        }

        // ---- norm sums (feeds rsqrt) ----
        float s0 = 0.f, s1 = 0.f, s2 = 0.f, s3 = 0.f;
#pragma unroll
        for (int c = 0; c < 32; c += 4) {
            s0 = fmaf(acc[c + 0], acc[c + 0], s0);
            s1 = fmaf(acc[c + 1], acc[c + 1], s1);
            s2 = fmaf(acc[c + 2], acc[c + 2], s2);
            s3 = fmaf(acc[c + 3], acc[c + 3], s3);
        }
        float rn = rsqrtf(0.25f * ((s0 + s1) + (s2 + s3)));

        // ---- projection on UNNORMALIZED acc (runs concurrent with rsqrt) ----
        float pd[6];
#pragma unroll
        for (int d = 0; d < 6; d++) {
            float p0 = 0.f, p1 = 0.f, p2 = 0.f, p3 = 0.f;
#pragma unroll
            for (int c4 = 0; c4 < 8; c4++) {
                float4 w = *(const float4*)(wo + d * 32 + c4 * 4);
                p0 = fmaf(acc[c4 * 4 + 0], w.x, p0);
                p1 = fmaf(acc[c4 * 4 + 1], w.y, p1);
                p2 = fmaf(acc[c4 * 4 + 2], w.z, p2);
                p3 = fmaf(acc[c4 * 4 + 3], w.w, p3);
            }
            pd[d] = ((p0 + p1) + (p2 + p3)) * rn;
        }

        // ---- scale psi ----
#pragma unroll
        for (int c = 0; c < 32; c++) P[c] = acc[c] * rn;

        // ---- store partials (3 x float2, 8B-aligned: h*26 + ci*6 even) ----
        {
            float2* pp = (float2*)&sPart[(t >> 1) & 1][t & 1][h][ci * 6];
            pp[0] = make_float2(pd[0], pd[1]);
            pp[1] = make_float2(pd[2], pd[3]);
            pp[2] = make_float2(pd[4], pd[5]);
        }

        // ---- barrier + reduce only every 2nd step (2-warp barrier) ----
        if (t & 1) {
            __syncthreads();
            if (is_red) {
                const int gb = (t >> 1) & 1;
                float sa = boutr + rxA;
                float sb = boutr + rxB;
#pragma unroll
                for (int hh = 0; hh < 16; hh++) {
                    sa += sPart[gb][0][hh][rci * 6 + rd];
                    sb += sPart[gb][1][hh][rci * 6 + rd];
                }
                out[obase + (size_t)(t - 1) * 384] = sa;
                out[obase + (size_t)t * 384]       = sb;
                // prefetch x for next group's outputs
                int ta = (t + 1 < 256) ? (t + 1) : 255;
                int tb = (t + 2 < 256) ? (t + 2) : 255;
                rxA = __ldg(x + obase + (size_t)ta * 384);
                rxB = __ldg(x + obase + (size_t)tb * 384);
            }
        }
    }
}

extern "C" void kernel_launch(void* const* d_in, const int* in_sizes, int n_in,
                              void* d_out, int out_size)
{
    const float* x    = (const float*)d_in[0];
    const float* Win  = (const float*)d_in[1];
    const float* bin  = (const float*)d_in[2];
    const float* Wout = (const float*)d_in[3];
    const float* bout = (const float*)d_in[4];
    float* out = (float*)d_out;

    prep_kernel<<<1, 256>>>(Win, bin, Wout);
    versor_kernel<<<256, BLK>>>(x, bout, out);
}